// round 1
// baseline (speedup 1.0000x reference)
#include <cuda_runtime.h>
#include <math.h>

// Problem-shape constants (fixed-shape problem; E taken from in_sizes).
#define MAX_NODES 100000
#define NGRAPH    32

// Device scratch (allocation-free rule: static __device__ arrays).
static __device__ float  g_ld[MAX_NODES];        // local density per node
static __device__ float  g_coef[MAX_NODES];      // dE/d(local_density) per node
static __device__ float4 g_f4[MAX_NODES];        // padded force accumulators (xyz, pad)
static __device__ float  g_enode[NGRAPH];
static __device__ float  g_eedge[NGRAPH];

__device__ __forceinline__ float softplus_f(float x) {
    return (x > 20.0f) ? x : log1pf(__expf(x));
}

// Vector f32 reduction (sm_90+): one L2 transaction for 3 components.
__device__ __forceinline__ void red_add_v4(float4* p, float x, float y, float z) {
    asm volatile("red.global.add.v4.f32 [%0], {%1, %2, %3, %4};"
                 :: "l"(p), "f"(x), "f"(y), "f"(z), "f"(0.0f)
                 : "memory");
}

__global__ void k_init(int N) {
    int i = blockIdx.x * blockDim.x + threadIdx.x;
    if (i < N) {
        g_ld[i] = 0.0f;
        g_f4[i] = make_float4(0.0f, 0.0f, 0.0f, 0.0f);
    }
    if (i < NGRAPH) {
        g_enode[i] = 0.0f;
        g_eedge[i] = 0.0f;
    }
}

__global__ void k_edge_fwd(const float* __restrict__ r,
                           const int*   __restrict__ dst,
                           const int*   __restrict__ n2g,
                           const float* __restrict__ pAd, const float* __restrict__ pLd,
                           const float* __restrict__ pAr, const float* __restrict__ pLr,
                           int E) {
    __shared__ float sE[NGRAPH];
    if (threadIdx.x < NGRAPH) sE[threadIdx.x] = 0.0f;
    __syncthreads();

    const float Ad = softplus_f(__ldg(pAd));
    const float Ld = softplus_f(__ldg(pLd));
    const float Ar = softplus_f(__ldg(pAr));
    const float Lr = softplus_f(__ldg(pLr));

    const int stride = gridDim.x * blockDim.x;
    for (int e = blockIdx.x * blockDim.x + threadIdx.x; e < E; e += stride) {
        float rx = __ldg(r + 3 * e + 0);
        float ry = __ldg(r + 3 * e + 1);
        float rz = __ldg(r + 3 * e + 2);
        float b  = sqrtf(rx * rx + ry * ry + rz * rz);
        int   d  = __ldg(dst + e);
        float dens = Ad * __expf(-Ld * b);
        atomicAdd(&g_ld[d], dens);
        float rep  = Ar * __expf(-Lr * b);
        atomicAdd(&sE[__ldg(n2g + d)], rep);
    }

    __syncthreads();
    if (threadIdx.x < NGRAPH) atomicAdd(&g_eedge[threadIdx.x], sE[threadIdx.x]);
}

__global__ void k_node(const int* __restrict__ n2g,
                       const float* __restrict__ pAe,
                       int N) {
    __shared__ float sE[NGRAPH];
    if (threadIdx.x < NGRAPH) sE[threadIdx.x] = 0.0f;
    __syncthreads();

    const float Ae = softplus_f(__ldg(pAe));
    int i = blockIdx.x * blockDim.x + threadIdx.x;
    if (i < N) {
        float ld = g_ld[i];
        float F, c;
        if (ld > 1e-12f) {
            float rs = rsqrtf(ld);
            F = -Ae * ld * rs;       // -Ae * sqrt(ld)
            c = -0.5f * Ae * rs;     // d(-Ae*sqrt(ld))/d(ld)
        } else {
            F = -Ae * 1e-6f;         // -Ae * sqrt(1e-12), grad clamped to 0
            c = 0.0f;
        }
        g_coef[i] = c;
        atomicAdd(&sE[__ldg(n2g + i)], F);
    }

    __syncthreads();
    if (threadIdx.x < NGRAPH) atomicAdd(&g_enode[threadIdx.x], sE[threadIdx.x]);
}

__global__ void k_edge_bwd(const float* __restrict__ r,
                           const int*   __restrict__ src,
                           const int*   __restrict__ dst,
                           const float* __restrict__ pAd, const float* __restrict__ pLd,
                           const float* __restrict__ pAr, const float* __restrict__ pLr,
                           int E) {
    const float Ad = softplus_f(__ldg(pAd));
    const float Ld = softplus_f(__ldg(pLd));
    const float Ar = softplus_f(__ldg(pAr));
    const float Lr = softplus_f(__ldg(pLr));

    const int stride = gridDim.x * blockDim.x;
    for (int e = blockIdx.x * blockDim.x + threadIdx.x; e < E; e += stride) {
        float rx = __ldg(r + 3 * e + 0);
        float ry = __ldg(r + 3 * e + 1);
        float rz = __ldg(r + 3 * e + 2);
        float b  = sqrtf(rx * rx + ry * ry + rz * rz);
        int   d  = __ldg(dst + e);
        int   s  = __ldg(src + e);

        float dens = Ad * __expf(-Ld * b);
        float rep  = Ar * __expf(-Lr * b);
        float c    = __ldg(&g_coef[d]);

        // dE/d(bondlen)
        float dEdb  = -c * Ld * dens - Lr * rep;
        float scale = dEdb / b;
        float dx = scale * rx;
        float dy = scale * ry;
        float dz = scale * rz;

        // forces = segsum(-dE_dr, dst) + segsum(+dE_dr, src)
        red_add_v4(&g_f4[d], -dx, -dy, -dz);
        red_add_v4(&g_f4[s],  dx,  dy,  dz);
    }
}

__global__ void k_final(float* __restrict__ out, int N) {
    int i = blockIdx.x * blockDim.x + threadIdx.x;
    if (i < NGRAPH) out[i] = g_enode[i] + g_eedge[i];
    int total = 3 * N;
    if (i < total) {
        int n = i / 3;
        int k = i - 3 * n;
        const float* f = (const float*)g_f4;
        out[NGRAPH + i] = f[4 * n + k];
    }
}

extern "C" void kernel_launch(void* const* d_in, const int* in_sizes, int n_in,
                              void* d_out, int out_size) {
    const float* r   = (const float*)d_in[0];
    const int*   src = (const int*)  d_in[1];
    const int*   dst = (const int*)  d_in[2];
    const int*   n2g = (const int*)  d_in[3];
    const float* pAd = (const float*)d_in[4];
    const float* pLd = (const float*)d_in[5];
    const float* pAr = (const float*)d_in[6];
    const float* pLr = (const float*)d_in[7];
    const float* pAe = (const float*)d_in[8];

    int E = in_sizes[1];   // src count
    int N = in_sizes[3];   // node2graph count
    if (N > MAX_NODES) N = MAX_NODES;

    float* out = (float*)d_out;
    const int B = 256;

    int gridN = (N + B - 1) / B;
    int gridE = (E + B - 1) / B;
    if (gridE > 1184) gridE = 1184;          // persistent grid-stride (148 SMs * 8 blocks)
    int gridF = (3 * N + B - 1) / B;

    k_init<<<gridN, B>>>(N);
    k_edge_fwd<<<gridE, B>>>(r, dst, n2g, pAd, pLd, pAr, pLr, E);
    k_node<<<gridN, B>>>(n2g, pAe, N);
    k_edge_bwd<<<gridE, B>>>(r, src, dst, pAd, pLd, pAr, pLr, E);
    k_final<<<gridF, B>>>(out, N);
}

// round 3
// speedup vs baseline: 1.0107x; 1.0107x over previous
#include <cuda_runtime.h>
#include <math.h>

#define MAX_NODES 100000
#define NGRAPH    32

static __device__ float  g_ld[MAX_NODES];        // local density per node
static __device__ float  g_coef[MAX_NODES];      // dE/d(local_density) per node
static __device__ float4 g_f4[MAX_NODES];        // padded force accumulators
static __device__ float  g_enode[NGRAPH];
static __device__ float  g_eedge[NGRAPH];

__device__ __forceinline__ float softplus_f(float x) {
    return (x > 20.0f) ? x : log1pf(__expf(x));
}

__device__ __forceinline__ void red_add_v4(float4* p, float x, float y, float z) {
    asm volatile("red.global.add.v4.f32 [%0], {%1, %2, %3, %4};"
                 :: "l"(p), "f"(x), "f"(y), "f"(z), "f"(0.0f)
                 : "memory");
}

__global__ void k_init(int N) {
    int i = blockIdx.x * blockDim.x + threadIdx.x;
    if (i < N) {
        g_ld[i] = 0.0f;
        g_f4[i] = make_float4(0.0f, 0.0f, 0.0f, 0.0f);
    }
    if (i < NGRAPH) {
        g_enode[i] = 0.0f;
        g_eedge[i] = 0.0f;
    }
}

// ---------------- forward: density scatter + repulsive graph sum ------------
__device__ __forceinline__ void fwd_one(float rx, float ry, float rz,
                                        int d, int g,
                                        float Ad, float Ld, float Ar, float Lr,
                                        float* sE) {
    float b = sqrtf(rx * rx + ry * ry + rz * rz);
    float dens = Ad * __expf(-Ld * b);
    float rep  = Ar * __expf(-Lr * b);
    atomicAdd(&g_ld[d], dens);
    atomicAdd(&sE[g], rep);
}

__global__ void k_edge_fwd(const float* __restrict__ r,
                           const int*   __restrict__ dst,
                           const int*   __restrict__ n2g,
                           const float* __restrict__ pAd, const float* __restrict__ pLd,
                           const float* __restrict__ pAr, const float* __restrict__ pLr,
                           int E) {
    __shared__ float sE[NGRAPH];
    if (threadIdx.x < NGRAPH) sE[threadIdx.x] = 0.0f;
    __syncthreads();

    const float Ad = softplus_f(__ldg(pAd));
    const float Ld = softplus_f(__ldg(pLd));
    const float Ar = softplus_f(__ldg(pAr));
    const float Lr = softplus_f(__ldg(pLr));

    const int tid    = blockIdx.x * blockDim.x + threadIdx.x;
    const int stride = gridDim.x * blockDim.x;
    const int nq     = E >> 2;

    const float4* r4 = (const float4*)r;
    const int4*   d4 = (const int4*)dst;

    for (int q = tid; q < nq; q += stride) {
        // front-batch all loads before any atomics -> high MLP
        float4 A = __ldg(r4 + 3 * q + 0);
        float4 B = __ldg(r4 + 3 * q + 1);
        float4 C = __ldg(r4 + 3 * q + 2);
        int4   D = __ldg(d4 + q);
        int g0 = __ldg(n2g + D.x);
        int g1 = __ldg(n2g + D.y);
        int g2 = __ldg(n2g + D.z);
        int g3 = __ldg(n2g + D.w);
        fwd_one(A.x, A.y, A.z, D.x, g0, Ad, Ld, Ar, Lr, sE);
        fwd_one(A.w, B.x, B.y, D.y, g1, Ad, Ld, Ar, Lr, sE);
        fwd_one(B.z, B.w, C.x, D.z, g2, Ad, Ld, Ar, Lr, sE);
        fwd_one(C.y, C.z, C.w, D.w, g3, Ad, Ld, Ar, Lr, sE);
    }
    for (int e = 4 * nq + tid; e < E; e += stride) {
        int d = __ldg(dst + e);
        fwd_one(__ldg(r + 3 * e), __ldg(r + 3 * e + 1), __ldg(r + 3 * e + 2),
                d, __ldg(n2g + d), Ad, Ld, Ar, Lr, sE);
    }

    __syncthreads();
    if (threadIdx.x < NGRAPH) atomicAdd(&g_eedge[threadIdx.x], sE[threadIdx.x]);
}

// ---------------- node pass: embedding + grad coefficient -------------------
__global__ void k_node(const int* __restrict__ n2g,
                       const float* __restrict__ pAe,
                       int N) {
    __shared__ float sE[NGRAPH];
    if (threadIdx.x < NGRAPH) sE[threadIdx.x] = 0.0f;
    __syncthreads();

    const float Ae = softplus_f(__ldg(pAe));
    int i = blockIdx.x * blockDim.x + threadIdx.x;
    if (i < N) {
        float ld = g_ld[i];
        float F, c;
        if (ld > 1e-12f) {
            float rs = rsqrtf(ld);
            F = -Ae * ld * rs;
            c = -0.5f * Ae * rs;
        } else {
            F = -Ae * 1e-6f;
            c = 0.0f;
        }
        g_coef[i] = c;
        atomicAdd(&sE[__ldg(n2g + i)], F);
    }

    __syncthreads();
    if (threadIdx.x < NGRAPH) atomicAdd(&g_enode[threadIdx.x], sE[threadIdx.x]);
}

// ---------------- backward: force scatter -----------------------------------
__device__ __forceinline__ void bwd_one(float rx, float ry, float rz,
                                        int d, int s, float c,
                                        float Ad, float Ld, float Ar, float Lr) {
    float b2    = rx * rx + ry * ry + rz * rz;
    float inv_b = rsqrtf(b2);
    float b     = b2 * inv_b;
    float dens  = Ad * __expf(-Ld * b);
    float rep   = Ar * __expf(-Lr * b);
    float dEdb  = -c * Ld * dens - Lr * rep;
    float scale = dEdb * inv_b;
    float dx = scale * rx, dy = scale * ry, dz = scale * rz;
    red_add_v4(&g_f4[d], -dx, -dy, -dz);
    red_add_v4(&g_f4[s],  dx,  dy,  dz);
}

__global__ void k_edge_bwd(const float* __restrict__ r,
                           const int*   __restrict__ src,
                           const int*   __restrict__ dst,
                           const float* __restrict__ pAd, const float* __restrict__ pLd,
                           const float* __restrict__ pAr, const float* __restrict__ pLr,
                           int E) {
    const float Ad = softplus_f(__ldg(pAd));
    const float Ld = softplus_f(__ldg(pLd));
    const float Ar = softplus_f(__ldg(pAr));
    const float Lr = softplus_f(__ldg(pLr));

    const int tid    = blockIdx.x * blockDim.x + threadIdx.x;
    const int stride = gridDim.x * blockDim.x;
    const int nq     = E >> 2;

    const float4* r4 = (const float4*)r;
    const int4*   d4 = (const int4*)dst;
    const int4*   s4 = (const int4*)src;

    for (int q = tid; q < nq; q += stride) {
        // front-batch all loads: 3x LDG.128 (r), 2x LDG.128 (indices),
        // then 4 independent coef gathers -> high MLP
        float4 A = __ldg(r4 + 3 * q + 0);
        float4 B = __ldg(r4 + 3 * q + 1);
        float4 C = __ldg(r4 + 3 * q + 2);
        int4   D = __ldg(d4 + q);
        int4   S = __ldg(s4 + q);
        float c0 = __ldg(&g_coef[D.x]);
        float c1 = __ldg(&g_coef[D.y]);
        float c2 = __ldg(&g_coef[D.z]);
        float c3 = __ldg(&g_coef[D.w]);

        bwd_one(A.x, A.y, A.z, D.x, S.x, c0, Ad, Ld, Ar, Lr);
        bwd_one(A.w, B.x, B.y, D.y, S.y, c1, Ad, Ld, Ar, Lr);
        bwd_one(B.z, B.w, C.x, D.z, S.z, c2, Ad, Ld, Ar, Lr);
        bwd_one(C.y, C.z, C.w, D.w, S.w, c3, Ad, Ld, Ar, Lr);
    }
    for (int e = 4 * nq + tid; e < E; e += stride) {
        int d = __ldg(dst + e), s = __ldg(src + e);
        bwd_one(__ldg(r + 3 * e), __ldg(r + 3 * e + 1), __ldg(r + 3 * e + 2),
                d, s, __ldg(&g_coef[d]), Ad, Ld, Ar, Lr);
    }
}

__global__ void k_final(float* __restrict__ out, int N) {
    int i = blockIdx.x * blockDim.x + threadIdx.x;
    if (i < NGRAPH) out[i] = g_enode[i] + g_eedge[i];
    int total = 3 * N;
    if (i < total) {
        int n = i / 3;
        int k = i - 3 * n;
        const float* f = (const float*)g_f4;
        out[NGRAPH + i] = f[4 * n + k];
    }
}

extern "C" void kernel_launch(void* const* d_in, const int* in_sizes, int n_in,
                              void* d_out, int out_size) {
    const float* r   = (const float*)d_in[0];
    const int*   src = (const int*)  d_in[1];
    const int*   dst = (const int*)  d_in[2];
    const int*   n2g = (const int*)  d_in[3];
    const float* pAd = (const float*)d_in[4];
    const float* pLd = (const float*)d_in[5];
    const float* pAr = (const float*)d_in[6];
    const float* pLr = (const float*)d_in[7];
    const float* pAe = (const float*)d_in[8];

    int E = in_sizes[1];
    int N = in_sizes[3];
    if (N > MAX_NODES) N = MAX_NODES;

    float* out = (float*)d_out;
    const int B = 256;

    int gridN = (N + B - 1) / B;
    int gridE = ((E >> 2) + B - 1) / B;
    if (gridE > 1184) gridE = 1184;
    int gridF = (3 * N + B - 1) / B;

    k_init<<<gridN, B>>>(N);
    k_edge_fwd<<<gridE, B>>>(r, dst, n2g, pAd, pLd, pAr, pLr, E);
    k_node<<<gridN, B>>>(n2g, pAe, N);
    k_edge_bwd<<<gridE, B>>>(r, src, dst, pAd, pLd, pAr, pLr, E);
    k_final<<<gridF, B>>>(out, N);
}

// round 5
// speedup vs baseline: 1.2001x; 1.1874x over previous
#include <cuda_runtime.h>
#include <math.h>

#define MAX_NODES 100000
#define NGRAPH    32

// Self-cleaning scratch: zero at module load; each kernel that consumes a
// buffer re-zeroes it for the next graph replay.
static __device__ float2 g_nd[MAX_NODES];        // {density, rep} per node
static __device__ float  g_coef[MAX_NODES];      // dE/d(local_density) per node
static __device__ float4 g_f4[MAX_NODES];        // padded force accumulators
static __device__ float  g_enode[NGRAPH];
static __device__ float  g_eedge[NGRAPH];

__device__ __forceinline__ float softplus_f(float x) {
    return (x > 20.0f) ? x : log1pf(__expf(x));
}

__device__ __forceinline__ void red_add_v2(float2* p, float x, float y) {
    asm volatile("red.global.add.v2.f32 [%0], {%1, %2};"
                 :: "l"(p), "f"(x), "f"(y)
                 : "memory");
}

__device__ __forceinline__ void red_add_v4(float4* p, float x, float y, float z) {
    asm volatile("red.global.add.v4.f32 [%0], {%1, %2, %3, %4};"
                 :: "l"(p), "f"(x), "f"(y), "f"(z), "f"(0.0f)
                 : "memory");
}

// ---------------- forward: fused {density, rep} scatter ---------------------
// e_edge(g) = sum_e rep_e [graph(dst_e)=g] == graph-sum of per-node rep sums,
// so rep rides in the same per-node vector RED as density. This removes the
// per-edge smem graph atomic AND the per-edge n2g gather entirely.
__device__ __forceinline__ void fwd_one(float rx, float ry, float rz, int d,
                                        float Ad, float Ld, float Ar, float Lr) {
    float b = sqrtf(rx * rx + ry * ry + rz * rz);
    float dens = Ad * __expf(-Ld * b);
    float rep  = Ar * __expf(-Lr * b);
    red_add_v2(&g_nd[d], dens, rep);
}

__global__ void k_edge_fwd(const float* __restrict__ r,
                           const int*   __restrict__ dst,
                           const float* __restrict__ pAd, const float* __restrict__ pLd,
                           const float* __restrict__ pAr, const float* __restrict__ pLr,
                           int E) {
    const float Ad = softplus_f(__ldg(pAd));
    const float Ld = softplus_f(__ldg(pLd));
    const float Ar = softplus_f(__ldg(pAr));
    const float Lr = softplus_f(__ldg(pLr));

    const int tid    = blockIdx.x * blockDim.x + threadIdx.x;
    const int stride = gridDim.x * blockDim.x;
    const int nq     = E >> 2;

    const float4* r4 = (const float4*)r;
    const int4*   d4 = (const int4*)dst;

    for (int q = tid; q < nq; q += stride) {
        float4 A = __ldg(r4 + 3 * q + 0);
        float4 B = __ldg(r4 + 3 * q + 1);
        float4 C = __ldg(r4 + 3 * q + 2);
        int4   D = __ldg(d4 + q);
        fwd_one(A.x, A.y, A.z, D.x, Ad, Ld, Ar, Lr);
        fwd_one(A.w, B.x, B.y, D.y, Ad, Ld, Ar, Lr);
        fwd_one(B.z, B.w, C.x, D.z, Ad, Ld, Ar, Lr);
        fwd_one(C.y, C.z, C.w, D.w, Ad, Ld, Ar, Lr);
    }
    for (int e = 4 * nq + tid; e < E; e += stride) {
        fwd_one(__ldg(r + 3 * e), __ldg(r + 3 * e + 1), __ldg(r + 3 * e + 2),
                __ldg(dst + e), Ad, Ld, Ar, Lr);
    }
}

// ---------------- node pass: embedding, grad coef, graph readouts -----------
__global__ void k_node(const int* __restrict__ n2g,
                       const float* __restrict__ pAe,
                       int N) {
    __shared__ float sF[NGRAPH];
    __shared__ float sR[NGRAPH];
    if (threadIdx.x < NGRAPH) { sF[threadIdx.x] = 0.0f; sR[threadIdx.x] = 0.0f; }
    __syncthreads();

    const float Ae = softplus_f(__ldg(pAe));
    int i = blockIdx.x * blockDim.x + threadIdx.x;
    if (i < N) {
        float2 v  = g_nd[i];
        float  ld = v.x;
        float F, c;
        if (ld > 1e-12f) {
            float rs = rsqrtf(ld);
            F = -Ae * ld * rs;
            c = -0.5f * Ae * rs;
        } else {
            F = -Ae * 1e-6f;
            c = 0.0f;
        }
        g_coef[i] = c;
        g_nd[i]   = make_float2(0.0f, 0.0f);   // self-clean for next replay
        int g = __ldg(n2g + i);
        atomicAdd(&sF[g], F);
        atomicAdd(&sR[g], v.y);
    }

    __syncthreads();
    if (threadIdx.x < NGRAPH) {
        atomicAdd(&g_enode[threadIdx.x], sF[threadIdx.x]);
        atomicAdd(&g_eedge[threadIdx.x], sR[threadIdx.x]);
    }
}

// ---------------- backward: force scatter -----------------------------------
__device__ __forceinline__ void bwd_one(float rx, float ry, float rz,
                                        int d, int s, float c,
                                        float Ad, float Ld, float Ar, float Lr) {
    float b2    = rx * rx + ry * ry + rz * rz;
    float inv_b = rsqrtf(b2);
    float b     = b2 * inv_b;
    float dens  = Ad * __expf(-Ld * b);
    float rep   = Ar * __expf(-Lr * b);
    float dEdb  = -c * Ld * dens - Lr * rep;
    float scale = dEdb * inv_b;
    float dx = scale * rx, dy = scale * ry, dz = scale * rz;
    red_add_v4(&g_f4[d], -dx, -dy, -dz);
    red_add_v4(&g_f4[s],  dx,  dy,  dz);
}

__global__ void k_edge_bwd(const float* __restrict__ r,
                           const int*   __restrict__ src,
                           const int*   __restrict__ dst,
                           const float* __restrict__ pAd, const float* __restrict__ pLd,
                           const float* __restrict__ pAr, const float* __restrict__ pLr,
                           int E) {
    const float Ad = softplus_f(__ldg(pAd));
    const float Ld = softplus_f(__ldg(pLd));
    const float Ar = softplus_f(__ldg(pAr));
    const float Lr = softplus_f(__ldg(pLr));

    const int tid    = blockIdx.x * blockDim.x + threadIdx.x;
    const int stride = gridDim.x * blockDim.x;
    const int no     = E >> 3;                 // 8 edges per iteration

    const float4* r4 = (const float4*)r;
    const int4*   d4 = (const int4*)dst;
    const int4*   s4 = (const int4*)src;

    for (int q = tid; q < no; q += stride) {
        // front-batch ALL loads for 8 edges: 6x LDG.128 (r), 4x LDG.128
        // (indices), then 8 independent scattered coef gathers -> deep MLP.
        float rr[24];
        #pragma unroll
        for (int j = 0; j < 6; j++) {
            float4 V = __ldg(r4 + 6 * q + j);
            rr[4 * j + 0] = V.x; rr[4 * j + 1] = V.y;
            rr[4 * j + 2] = V.z; rr[4 * j + 3] = V.w;
        }
        int4 D0 = __ldg(d4 + 2 * q + 0);
        int4 D1 = __ldg(d4 + 2 * q + 1);
        int4 S0 = __ldg(s4 + 2 * q + 0);
        int4 S1 = __ldg(s4 + 2 * q + 1);
        int dd[8] = {D0.x, D0.y, D0.z, D0.w, D1.x, D1.y, D1.z, D1.w};
        int ss[8] = {S0.x, S0.y, S0.z, S0.w, S1.x, S1.y, S1.z, S1.w};
        float cc[8];
        #pragma unroll
        for (int k = 0; k < 8; k++) cc[k] = __ldg(&g_coef[dd[k]]);

        #pragma unroll
        for (int k = 0; k < 8; k++) {
            bwd_one(rr[3 * k], rr[3 * k + 1], rr[3 * k + 2],
                    dd[k], ss[k], cc[k], Ad, Ld, Ar, Lr);
        }
    }
    for (int e = 8 * no + tid; e < E; e += stride) {
        int d = __ldg(dst + e), s = __ldg(src + e);
        bwd_one(__ldg(r + 3 * e), __ldg(r + 3 * e + 1), __ldg(r + 3 * e + 2),
                d, s, __ldg(&g_coef[d]), Ad, Ld, Ar, Lr);
    }
}

// ---------------- finalize: pack output, self-clean scratch -----------------
__global__ void k_final(float* __restrict__ out, int N) {
    int i = blockIdx.x * blockDim.x + threadIdx.x;
    if (i < NGRAPH) {
        out[i] = g_enode[i] + g_eedge[i];
        g_enode[i] = 0.0f;
        g_eedge[i] = 0.0f;
    }
    if (i < N) {
        float4 f = g_f4[i];
        out[NGRAPH + 3 * i + 0] = f.x;
        out[NGRAPH + 3 * i + 1] = f.y;
        out[NGRAPH + 3 * i + 2] = f.z;
        g_f4[i] = make_float4(0.0f, 0.0f, 0.0f, 0.0f);
    }
}

extern "C" void kernel_launch(void* const* d_in, const int* in_sizes, int n_in,
                              void* d_out, int out_size) {
    const float* r   = (const float*)d_in[0];
    const int*   src = (const int*)  d_in[1];
    const int*   dst = (const int*)  d_in[2];
    const int*   n2g = (const int*)  d_in[3];
    const float* pAd = (const float*)d_in[4];
    const float* pLd = (const float*)d_in[5];
    const float* pAr = (const float*)d_in[6];
    const float* pLr = (const float*)d_in[7];
    const float* pAe = (const float*)d_in[8];

    int E = in_sizes[1];
    int N = in_sizes[3];
    if (N > MAX_NODES) N = MAX_NODES;

    float* out = (float*)d_out;
    const int B = 256;

    int gridN = (N + B - 1) / B;
    int gridE = ((E >> 2) + B - 1) / B;
    if (gridE > 1184) gridE = 1184;
    int gridB = ((E >> 3) + B - 1) / B;
    if (gridB > 1184) gridB = 1184;

    k_edge_fwd<<<gridE, B>>>(r, dst, pAd, pLd, pAr, pLr, E);
    k_node<<<gridN, B>>>(n2g, pAe, N);
    k_edge_bwd<<<gridB, B>>>(r, src, dst, pAd, pLd, pAr, pLr, E);
    k_final<<<gridN, B>>>(out, N);
}